// round 8
// baseline (speedup 1.0000x reference)
#include <cuda_runtime.h>
#include <cstdint>

// QuantumLikeLayer: out[b,:] = CZ_diag * (H^{⊗11} @ in[b,:]), N=2048, FWHT.
// TWO warps per row (64 threads, 32 elems/thread, 16 u64 f32x2 regs),
// zero shuffles, two XOR-swizzled smem exchanges, 3 register phases:
//   load (fuse i0): regs {i1,i8,i9,i10}  -> P1 (4 stages)
//   exch1 -> regs {i3(k-parity), i4,i5,i2} -> P2 (4 stages) -> CZ+scale
//   exch2 -> regs {i1(pair), i6,i7,i10}  -> P3 (i6,i7) -> coalesced STG.128
// + L2 bulk prefetch one wave ahead, __ldcs/__stcs streaming hints.

#define NN 2048
#define PF_ROWS 1776   // one wave: 148 SMs x 6 CTAs x 2 rows
typedef unsigned long long u64;

__device__ __forceinline__ u64 pk(float x, float y) {
    u64 d; asm("mov.b64 %0,{%1,%2};" : "=l"(d) : "f"(x), "f"(y)); return d;
}
__device__ __forceinline__ void upk(u64 v, float& x, float& y) {
    asm("mov.b64 {%0,%1},%2;" : "=f"(x), "=f"(y) : "l"(v));
}
__device__ __forceinline__ u64 padd(u64 a, u64 b) {
    u64 d; asm("add.rn.f32x2 %0,%1,%2;" : "=l"(d) : "l"(a), "l"(b)); return d;
}
__device__ __forceinline__ u64 pfma(u64 a, u64 b, u64 c) {
    u64 d; asm("fma.rn.f32x2 %0,%1,%2,%3;" : "=l"(d) : "l"(a), "l"(b), "l"(c)); return d;
}
__device__ __forceinline__ u64 pmul(u64 a, u64 b) {
    u64 d; asm("mul.rn.f32x2 %0,%1,%2;" : "=l"(d) : "l"(a), "l"(b)); return d;
}

template <int M>
__device__ __forceinline__ void bfly16(u64 v[16], u64 NEG1) {
#pragma unroll
    for (int r = 0; r < 16; r++) {
        if (!(r & M)) {
            u64 a = v[r], b = v[r | M];
            v[r]     = padd(a, b);
            v[r | M] = pfma(b, NEG1, a);   // a - b
        }
    }
}

__global__ void __launch_bounds__(128, 6)
fwht_cz_kernel(const float4* __restrict__ in, float4* __restrict__ out, int rows) {
    __shared__ u64 smA[2][1024];   // exch1 buffers, one per warp-pair (8KB each)
    __shared__ u64 smB[2][1024];   // exch2 buffers

    const int tid  = threadIdx.x;
    const int pair = tid >> 6;          // 0,1: which row of this CTA
    const int t    = tid & 63;          // thread-in-pair (6 bits)
    const int w    = (tid >> 5) & 1;    // warp-in-pair (t bit 5)

    const int row = (blockIdx.x << 1) + pair;
    const float4* __restrict__ ip = in  + (size_t)row * (NN / 4);
    float4* __restrict__       op = out + (size_t)row * (NN / 4);
    u64* sA = smA[pair];
    u64* sB = smB[pair];

    // ---- L2 bulk prefetch for the row this slot owns one wave later ----
    if (t == 0) {
        int pr = row + PF_ROWS;
        if (pr < rows) {
            const float4* g = in + (size_t)pr * (NN / 4);
            asm volatile("cp.async.bulk.prefetch.L2.global [%0], %1;"
                         :: "l"(g), "r"(8192) : "memory");
        }
    }

    const u64 NEG1 = pk(-1.0f, -1.0f);
    u64 v[16];

    // ---- load: f4 index f = t + 64j; t bits = i2..i7 (bit5=w), j = i8,i9,i10 ----
    // comps: x=(i0=0,i1=0) y=(1,0) z=(0,1) w=(1,1). Fuse i0; pack = i0.
    // reg r = i1 + 2*i8 + 4*i9 + 8*i10
#pragma unroll
    for (int j = 0; j < 8; j++) {
        float4 q = __ldcs(&ip[t + 64 * j]);
        v[2 * j]     = pk(q.x + q.y, q.x - q.y);   // i1 = 0
        v[2 * j + 1] = pk(q.z + q.w, q.z - q.w);   // i1 = 1
    }

    // ---- P1: i1, i8, i9, i10 ----
    bfly16<1>(v, NEG1); bfly16<2>(v, NEG1);
    bfly16<4>(v, NEG1); bfly16<8>(v, NEG1);

    // ---- exch1 write: STS.64 ----
    // target region tr (6 bits) = i1 + 2*i6 + 4*i7 + 8*i8 + 16*i10 + 32*i9
    // offset: k = i4 + 2*i5 + 4*i2 (3 bits), b = i3; slot = 16*tr + 2*(k^(tr&7)) + b
    {
        const int base_t = 2 * ((t >> 4) & 1) + 4 * w;              // 2*i6 + 4*i7
        const int k = ((t >> 2) & 1) + 2 * ((t >> 3) & 1) + 4 * (t & 1);
        const int b = (t >> 1) & 1;                                  // i3
#pragma unroll
        for (int r = 0; r < 16; r++) {
            int tr = base_t + (r & 1) + 8 * ((r >> 1) & 1)
                   + 32 * ((r >> 2) & 1) + 16 * ((r >> 3) & 1);
            sA[16 * tr + 2 * (k ^ (tr & 7)) + b] = v[r];
        }
    }
    __syncthreads();

    // ---- exch1 read: LDS.128; thread t owns 256B region ----
    // new t bit meaning: bit0=i1, bit1=i6, bit2=i7, bit3=i8, bit4=i10, bit5(w)=i9
    // reg v[2k+b]: b = i3, k = i4 + 2*i5 + 4*i2
    {
        const float4* f4 = (const float4*)sA;
        const int m7 = t & 7;
#pragma unroll
        for (int k = 0; k < 8; k++) {
            float4 q = f4[8 * t + (k ^ m7)];
            v[2 * k]     = pk(q.x, q.y);   // b = i3 = 0
            v[2 * k + 1] = pk(q.z, q.w);   // b = i3 = 1
        }
    }

    // ---- P2: i3, i4, i5, i2 ----
    bfly16<1>(v, NEG1); bfly16<2>(v, NEG1);
    bfly16<4>(v, NEG1); bfly16<8>(v, NEG1);

    // ---- CZ sign + 2^{-5.5}: i9 = t bit5, i10 = t bit4 -> thread-uniform ----
    // (commutes with remaining i6,i7 butterflies: diagonal doesn't involve i6,i7)
    {
        const float S = 0.022097086912079608f;   // 2^{-5.5}
        float sc = ((t & 48) == 48) ? -S : S;
        u64 sc2 = pk(sc, sc);
#pragma unroll
        for (int r = 0; r < 16; r++) v[r] = pmul(v[r], sc2);
    }

    // ---- exch2 write: STS.64 ----
    // sigma (6) = i2 + 2*i3 + 4*i4 + 8*i5 + 16*i8 + 32*i9
    // rho (4)   = i1 + 2*i6 + 4*i7 + 8*i10; slot = 16*sig + 2*((rho>>1)^(sig&7)) + (rho&1)
    {
        const int sig_hi = 16 * ((t >> 3) & 1) + 32 * w;            // i8, i9
        const int rho = (t & 7) + 8 * ((t >> 4) & 1);
        const int rh = rho >> 1, rl = rho & 1;
#pragma unroll
        for (int kk = 0; kk < 16; kk++) {     // kk = 2k + b
            int k = kk >> 1, b = kk & 1;
            int sig = ((k >> 2) & 1) + 2 * b + 4 * (k & 1)
                    + 8 * ((k >> 1) & 1) + sig_hi;
            sB[16 * sig + 2 * (rh ^ (sig & 7)) + rl] = v[kk];
        }
    }
    __syncthreads();

    // ---- exch2 read (LDS.128) + P3 (i6,i7) + coalesced STG.128 ----
    // new t bits: bit0=i2, bit1=i3, bit2=i4, bit3=i5, bit4=i8, bit5(w)=i9
    // u[rho]: rho = i1 + 2*g, g = i6 + 2*i7 + 4*i10
    {
        const float4* f4 = (const float4*)sB;
        const int m7 = t & 7;
        u64 u[16];
#pragma unroll
        for (int g = 0; g < 8; g++) {
            float4 q = f4[8 * t + (g ^ m7)];
            u[2 * g]     = pk(q.x, q.y);   // i1 = 0
            u[2 * g + 1] = pk(q.z, q.w);   // i1 = 1
        }
        bfly16<2>(u, NEG1);   // i6 (u idx bit1)
        bfly16<4>(u, NEG1);   // i7 (u idx bit2)

        // out f4 index f = i2345 + 16*i6 + 32*i7 + 64*i8 + 128*i9 + 256*i10
        const int fbase = (t & 15) + 64 * ((t >> 4) & 1) + 128 * w;
#pragma unroll
        for (int g = 0; g < 8; g++) {
            float a, b2, c, d;
            upk(u[2 * g], a, b2); upk(u[2 * g + 1], c, d);
            __stcs(&op[fbase + 16 * (g & 3) + 256 * (g >> 2)],
                   make_float4(a, b2, c, d));   // comps = (i0,i1): 00,10,01,11
        }
    }
}

extern "C" void kernel_launch(void* const* d_in, const int* in_sizes, int n_in,
                              void* d_out, int out_size) {
    const float4* in = (const float4*)d_in[0];
    float4* out = (float4*)d_out;
    const int rows = in_sizes[0] / NN;       // 16384
    fwht_cz_kernel<<<rows / 2, 128>>>(in, out, rows);
}